// round 8
// baseline (speedup 1.0000x reference)
#include <cuda_runtime.h>
#include <cuda_fp16.h>
#include <string.h>

// Problem constants
#define B_TOTAL 65536
#define CN 16
#define CC 16
#define DIM 128
#define VOC 65
#define EPSF 1e-5f

// Decomposition: D=128 in 2 chunks of 64. One warp handles TWO rows per
// iteration: lanes 0-15 -> row A, lanes 16-31 -> row B. Each lane owns a
// 4-element (8B fp16) slice of its row's 64-wide chunk.
// W is staged in SMEM (not registers) to free 32 regs for LDS MLP.
#define DCH 64
#define NCHUNK 2
#define NBX 74            // 74 * 2 = 148 CTAs = one per SM
#define NTHREADS 1024
#define NWARPS 32

// Shared memory:
//   emb_s : CC*VOC*DCH halves = 66560 halves = 133120 B (fp16 table chunk)
//   w_s   : CN*DCH halves = 1024 halves = 2048 B (fp16 W chunk)
//   slots : per-warp double-buffered: 2 bufs x 256 B = 512 B/warp -> 16384 B
#define EMB_HALVES (CC * VOC * DCH)
#define W_HALVES   (CN * DCH)
#define SLOTS_BYTES (NWARPS * 512)
#define SMEM_BYTES (EMB_HALVES * 2 + W_HALVES * 2 + SLOTS_BYTES)

__device__ __forceinline__ __half2 u2h2(unsigned u) {
    __half2 h; memcpy(&h, &u, 4); return h;
}

__global__ __launch_bounds__(NTHREADS, 1)
void embed_att_kernel(const float* __restrict__ x_num,
                      const float* __restrict__ means,
                      const float* __restrict__ stds,
                      const float* __restrict__ lin_W,
                      const float* __restrict__ lin_b,
                      const float* __restrict__ emb,
                      const int*   __restrict__ x_cat,
                      float*       __restrict__ out)
{
    extern __shared__ __align__(16) char smem_raw[];
    __half* emb_s = (__half*)smem_raw;
    __half* w_s   = emb_s + EMB_HALVES;
    char*   slots = smem_raw + (EMB_HALVES + W_HALVES) * 2;

    const int tid   = threadIdx.x;
    const int lane  = tid & 31;
    const int wrp   = tid >> 5;
    const int sub   = lane & 15;   // attr index (producer) / 8B slice owner
    const int grp   = lane >> 4;   // 0 = row A, 1 = row B
    const int chunk = blockIdx.y;
    const int dbase = chunk * DCH;

    // ---- Preload emb chunk into SMEM as fp16 (1040 vectors x 128B) ----
    for (int s = tid; s < CC * VOC * (DCH / 4); s += NTHREADS) {
        int vec = s >> 4;
        int jj  = (s & 15) * 4;
        float4 f = *(const float4*)(emb + (size_t)vec * DIM + dbase + jj);
        *(__half2*)(emb_s + vec * DCH + jj)     = __floats2half2_rn(f.x, f.y);
        *(__half2*)(emb_s + vec * DCH + jj + 2) = __floats2half2_rn(f.z, f.w);
    }
    // ---- Preload W chunk into SMEM as fp16 (16 attrs x 64 halves) ----
    if (tid < W_HALVES / 2) {
        int i = tid >> 5;            // attr
        int j = (tid & 31) * 2;      // d pair
        w_s[i * DCH + j]     = __float2half_rn(lin_W[i * DIM + dbase + j]);
        w_s[i * DCH + j + 1] = __float2half_rn(lin_W[i * DIM + dbase + j + 1]);
    }

    // ---- Per-lane constants ----
    const float invr = 1.0f / (stds[sub] + EPSF);
    const float c0   = -means[sub] * invr;
    const int   voff_bytes = sub * VOC * (DCH * 2);   // byte base for attr 'sub'

    // bias pre-summed in fp32 (kept fp32 for accuracy)
    float4 bias = make_float4(0.f, 0.f, 0.f, 0.f);
    #pragma unroll
    for (int i = 0; i < CN; i++) {
        float4 lb = *(const float4*)(lin_b + i * DIM + dbase + 4 * sub);
        bias.x += lb.x; bias.y += lb.y; bias.z += lb.z; bias.w += lb.w;
    }
    __syncthreads();

    // ---- Balanced row range ----
    const int bx    = blockIdx.x;
    const int start = (int)(((long long)bx       * B_TOTAL) / NBX);
    const int end   = (int)(((long long)(bx + 1) * B_TOTAL) / NBX);

    char* wslot = slots + wrp * 512;
    const char* myemb = (const char*)emb_s + 8 * sub;  // lane's 8B slice base
    const char* myw   = (const char*)w_s   + 8 * sub;  // lane's 8B W slice base
    const int slot_off = (sub >> 1) * 32 + grp * 16 + (sub & 1) * 8;
    int buf = 0;

    const __half2 h2z = __float2half2_rn(0.f);

    for (int b = start + wrp * 2; b < end; b += 2 * NWARPS) {
        const int  myrow = b + grp;
        const bool valid = myrow < end;

        // ---- Produce: this lane computes {gather offset, z} for (myrow, sub) ----
        float x = 0.f; int v = 0;
        if (valid) {
            x = x_num[myrow * CN + sub];
            v = x_cat[myrow * CC + sub];
        }
        float t = fmaf(x, invr, c0);
        float z = __fdividef(1.0f, 1.0f + __expf(-t));
        __half2 zz = __floats2half2_rn(z, z);
        int zb; memcpy(&zb, &zz, 4);
        *(int2*)(wslot + buf * 256 + slot_off) =
            make_int2(voff_bytes + v * (DCH * 2), zb);
        __syncwarp();

        // ---- Consume: 4 batches of {2 slots, 4 gathers, 4 W loads} ----
        const char* sl = wslot + buf * 256 + grp * 16;
        __half2 g00 = h2z, g01 = h2z, g10 = h2z, g11 = h2z;  // gather chains
        __half2 n0 = h2z, n1 = h2z;                           // numeric chains
        #pragma unroll
        for (int h = 0; h < 4; h++) {
            // two slot broadcasts (attrs 4h..4h+3)
            int4 p0 = *(const int4*)(sl + h * 64);        // {off,z} attrs 4h,4h+1
            int4 p1 = *(const int4*)(sl + h * 64 + 32);   // attrs 4h+2,4h+3
            // four gathers (LDS.64), addresses from slots
            uint2 qa = *(const uint2*)(myemb + p0.x);
            uint2 qb = *(const uint2*)(myemb + p0.z);
            uint2 qc = *(const uint2*)(myemb + p1.x);
            uint2 qd = *(const uint2*)(myemb + p1.z);
            // four W loads (LDS.64, compile-time offsets, broadcast across groups)
            uint2 w0 = *(const uint2*)(myw + (4 * h + 0) * (DCH * 2));
            uint2 w1 = *(const uint2*)(myw + (4 * h + 1) * (DCH * 2));
            uint2 w2 = *(const uint2*)(myw + (4 * h + 2) * (DCH * 2));
            uint2 w3 = *(const uint2*)(myw + (4 * h + 3) * (DCH * 2));
            // gather accumulation (4 independent chains)
            g00 = __hadd2(g00, u2h2(qa.x)); g01 = __hadd2(g01, u2h2(qa.y));
            g10 = __hadd2(g10, u2h2(qb.x)); g11 = __hadd2(g11, u2h2(qb.y));
            g00 = __hadd2(g00, u2h2(qc.x)); g01 = __hadd2(g01, u2h2(qc.y));
            g10 = __hadd2(g10, u2h2(qd.x)); g11 = __hadd2(g11, u2h2(qd.y));
            // numeric FMA chains
            __half2 zh0 = u2h2((unsigned)p0.y);
            __half2 zh1 = u2h2((unsigned)p0.w);
            __half2 zh2 = u2h2((unsigned)p1.y);
            __half2 zh3 = u2h2((unsigned)p1.w);
            n0 = __hfma2(zh0, u2h2(w0.x), n0); n1 = __hfma2(zh0, u2h2(w0.y), n1);
            n0 = __hfma2(zh1, u2h2(w1.x), n0); n1 = __hfma2(zh1, u2h2(w1.y), n1);
            n0 = __hfma2(zh2, u2h2(w2.x), n0); n1 = __hfma2(zh2, u2h2(w2.y), n1);
            n0 = __hfma2(zh3, u2h2(w3.x), n0); n1 = __hfma2(zh3, u2h2(w3.y), n1);
        }

        __half2 s0 = __hadd2(g00, __hadd2(g10, n0));
        __half2 s1 = __hadd2(g01, __hadd2(g11, n1));
        float2 f0 = __half22float2(s0);
        float2 f1 = __half22float2(s1);
        if (valid) {
            *(float4*)(out + (size_t)myrow * DIM + dbase + 4 * sub) =
                make_float4(bias.x + f0.x, bias.y + f0.y,
                            bias.z + f1.x, bias.w + f1.y);
        }
        buf ^= 1;
    }
}

extern "C" void kernel_launch(void* const* d_in, const int* in_sizes, int n_in,
                              void* d_out, int out_size)
{
    const float* x_num = (const float*)d_in[0];
    const float* means = (const float*)d_in[1];
    const float* stds  = (const float*)d_in[2];
    const float* lin_W = (const float*)d_in[3];
    const float* lin_b = (const float*)d_in[4];
    const float* emb   = (const float*)d_in[5];
    const int*   x_cat = (const int*)d_in[6];
    float* out = (float*)d_out;

    cudaFuncSetAttribute(embed_att_kernel,
                         cudaFuncAttributeMaxDynamicSharedMemorySize, SMEM_BYTES);

    dim3 grid(NBX, NCHUNK);
    embed_att_kernel<<<grid, NTHREADS, SMEM_BYTES>>>(
        x_num, means, stds, lin_W, lin_b, emb, x_cat, out);
}

// round 10
// speedup vs baseline: 1.2455x; 1.2455x over previous
#include <cuda_runtime.h>
#include <cuda_fp16.h>
#include <string.h>

// Problem constants
#define B_TOTAL 65536
#define CN 16
#define CC 16
#define DIM 128
#define VOC 65
#define EPSF 1e-5f

// Decomposition: D=128 in 2 chunks of 64. One warp handles TWO rows per
// iteration: lanes 0-15 -> row A, lanes 16-31 -> row B. Each lane owns an
// 8B fp16 slice of its row's 64-wide chunk.
// Table lives in a global fp16 mirror (L1D-cached, sector-level footprint
// 130KB/SM < 211KB L1D). SMEM holds only the per-warp slot buffers.
#define DCH 64
#define NCHUNK 2
#define NBX 74            // 74 * 2 = 148 CTAs = one per SM
#define NTHREADS 1024
#define NWARPS 32

#define EMB_VALS (CC * VOC * DIM)   // 133120 fp16 values = 266240 B mirror

__device__ __half2 d_emb16[EMB_VALS / 2];   // fp16 mirror of emb, full D

// ---- Kernel 0: convert emb fp32 -> fp16 mirror (runs every launch) ----
__global__ void convert_emb_kernel(const float* __restrict__ emb) {
    int i = blockIdx.x * blockDim.x + threadIdx.x;   // over half2 elements
    if (i < EMB_VALS / 2) {
        float2 f = *(const float2*)(emb + 2 * i);
        d_emb16[i] = __floats2half2_rn(f.x, f.y);
    }
}

__device__ __forceinline__ __half2 u2h2(unsigned u) {
    __half2 h; memcpy(&h, &u, 4); return h;
}

__global__ __launch_bounds__(NTHREADS, 1)
void embed_att_kernel(const float* __restrict__ x_num,
                      const float* __restrict__ means,
                      const float* __restrict__ stds,
                      const float* __restrict__ lin_W,
                      const float* __restrict__ lin_b,
                      const int*   __restrict__ x_cat,
                      float*       __restrict__ out)
{
    // Only slot buffers in SMEM: per warp 2 bufs x 256 B = 512 B -> 16 KB.
    __shared__ __align__(16) char slots[NWARPS * 512];

    const int tid   = threadIdx.x;
    const int lane  = tid & 31;
    const int wrp   = tid >> 5;
    const int sub   = lane & 15;   // attr index (producer) / 8B slice owner
    const int grp   = lane >> 4;   // 0 = row A, 1 = row B
    const int chunk = blockIdx.y;
    const int dbase = chunk * DCH;

    // ---- Per-lane constants ----
    const float invr = 1.0f / (stds[sub] + EPSF);
    const float c0   = -means[sub] * invr;
    const int   voff_bytes = sub * VOC * (DIM * 2);   // byte base for attr 'sub'

    // W slice (4 floats per attr) as 2x half2; bias pre-summed in fp32
    __half2 wa[CN], wb[CN];
    float4 bias = make_float4(0.f, 0.f, 0.f, 0.f);
    #pragma unroll
    for (int i = 0; i < CN; i++) {
        float4 wf = *(const float4*)(lin_W + i * DIM + dbase + 4 * sub);
        wa[i] = __floats2half2_rn(wf.x, wf.y);
        wb[i] = __floats2half2_rn(wf.z, wf.w);
        float4 lb = *(const float4*)(lin_b + i * DIM + dbase + 4 * sub);
        bias.x += lb.x; bias.y += lb.y; bias.z += lb.z; bias.w += lb.w;
    }

    // ---- Balanced row range ----
    const int bx    = blockIdx.x;
    const int start = (int)(((long long)bx       * B_TOTAL) / NBX);
    const int end   = (int)(((long long)(bx + 1) * B_TOTAL) / NBX);

    char* wslot = slots + wrp * 512;
    // Lane's gather base inside the fp16 mirror: chunk half + 8B slice.
    const char* myemb = (const char*)d_emb16 + chunk * (DCH * 2) + 8 * sub;
    const int slot_off = (sub >> 1) * 32 + grp * 16 + (sub & 1) * 8;
    int buf = 0;

    const __half2 h2z = __float2half2_rn(0.f);

    for (int b = start + wrp * 2; b < end; b += 2 * NWARPS) {
        const int  myrow = b + grp;
        const bool valid = myrow < end;

        // ---- Produce: {gather byte offset, z} for (myrow, sub) ----
        // Streaming hints keep x_num/x_cat out of L1 (protect the table).
        float x = 0.f; int v = 0;
        if (valid) {
            x = __ldcs(x_num + myrow * CN + sub);
            v = __ldcs(x_cat + myrow * CC + sub);
        }
        float t = fmaf(x, invr, c0);
        float z = __fdividef(1.0f, 1.0f + __expf(-t));
        __half2 zz = __floats2half2_rn(z, z);
        int zb; memcpy(&zb, &zz, 4);
        *(int2*)(wslot + buf * 256 + slot_off) =
            make_int2(voff_bytes + v * (DIM * 2), zb);
        __syncwarp();

        // ---- Consume: 8 slot broadcasts x {2 LDG gathers + 2 numeric} ----
        const char* sl = wslot + buf * 256 + grp * 16;
        __half2 g00 = h2z, g01 = h2z, g10 = h2z, g11 = h2z;
        __half2 n0 = h2z, n1 = h2z;
        #pragma unroll
        for (int e4 = 0; e4 < 8; e4++) {
            int4 p = *(const int4*)(sl + e4 * 32);        // {off0,z0,off1,z1}
            uint2 q0 = __ldg((const uint2*)(myemb + p.x)); // LDG.64 gather (L1)
            uint2 q1 = __ldg((const uint2*)(myemb + p.z));
            __half2 zh0 = u2h2((unsigned)p.y);
            __half2 zh1 = u2h2((unsigned)p.w);
            if (e4 < 4) {
                g00 = __hadd2(g00, u2h2(q0.x)); g01 = __hadd2(g01, u2h2(q0.y));
                g00 = __hadd2(g00, u2h2(q1.x)); g01 = __hadd2(g01, u2h2(q1.y));
            } else {
                g10 = __hadd2(g10, u2h2(q0.x)); g11 = __hadd2(g11, u2h2(q0.y));
                g10 = __hadd2(g10, u2h2(q1.x)); g11 = __hadd2(g11, u2h2(q1.y));
            }
            n0 = __hfma2(zh0, wa[2 * e4],     n0);
            n1 = __hfma2(zh0, wb[2 * e4],     n1);
            n0 = __hfma2(zh1, wa[2 * e4 + 1], n0);
            n1 = __hfma2(zh1, wb[2 * e4 + 1], n1);
        }

        __half2 s0 = __hadd2(__hadd2(g00, g10), n0);
        __half2 s1 = __hadd2(__hadd2(g01, g11), n1);
        float2 f0 = __half22float2(s0);
        float2 f1 = __half22float2(s1);
        if (valid) {
            float4 o = make_float4(bias.x + f0.x, bias.y + f0.y,
                                   bias.z + f1.x, bias.w + f1.y);
            __stcs((float4*)(out + (size_t)myrow * DIM + dbase + 4 * sub), o);
        }
        buf ^= 1;
    }
}

extern "C" void kernel_launch(void* const* d_in, const int* in_sizes, int n_in,
                              void* d_out, int out_size)
{
    const float* x_num = (const float*)d_in[0];
    const float* means = (const float*)d_in[1];
    const float* stds  = (const float*)d_in[2];
    const float* lin_W = (const float*)d_in[3];
    const float* lin_b = (const float*)d_in[4];
    const float* emb   = (const float*)d_in[5];
    const int*   x_cat = (const int*)d_in[6];
    float* out = (float*)d_out;

    // Kernel 0: refresh the fp16 mirror (deterministic, graph-capturable).
    convert_emb_kernel<<<(EMB_VALS / 2 + 255) / 256, 256>>>(emb);

    // Kernel 1: main fused kernel.
    dim3 grid(NBX, NCHUNK);
    embed_att_kernel<<<grid, NTHREADS>>>(
        x_num, means, stds, lin_W, lin_b, x_cat, out);
}